// round 6
// baseline (speedup 1.0000x reference)
#include <cuda_runtime.h>
#include <math.h>

#define NB 64
#define N 1024
#define ITERS 10
#define NCHUNK 8

// Scratch (allocation-free, static device memory)
__device__ __align__(16) float g_u[NB * N];
__device__ __align__(16) float g_v[NB * N];
__device__ __align__(16) float g_pm[NB * NCHUNK * N];
__device__ __align__(16) float g_ps[NB * NCHUNK * N];
// Quantized A (biased uint16) + per-row quant scale
__device__ __align__(16) unsigned short g_q[(size_t)NB * N * N];
__device__ __align__(16) float g_rs[NB * N];

// Dequant: A = as_float(0x4B000000 | u16) * s - 8421376 * s
#define QBIAS 8421376.0f   // 2^23 + 32768

__device__ __forceinline__ float clampA(float m) {
    return fminf(fmaxf(m, -25.0f), 25.0f) * 10.0f;   // clip(M,±25)/0.1
}

// ---------------------------------------------------------------------------
// Quantize A to biased uint16 with per-row scale; ALSO computes
// u1[r] = LSE_j(A[r][j]) (first row pass, v0 = 0) from the exact values.
// Block 256 = 4 rows x 64 threads; thread holds 16 values:
// float4 idx {2tr, 2tr+1, 128+2tr, 129+2tr} -> cols [8tr..8tr+7] and [512+8tr..+7].
// ---------------------------------------------------------------------------
__global__ void __launch_bounds__(256) quant_row1_kernel(const float* __restrict__ M) {
    int rl   = threadIdx.x >> 6;
    int tr   = threadIdx.x & 63;
    int half = tr >> 5;
    int lane = tr & 31;
    size_t r = (size_t)blockIdx.x * 4 + rl;

    const float4* __restrict__ row4 = reinterpret_cast<const float4*>(M) + r * (N / 4);

    float x[16];
    float mx = -1e30f, am = 0.0f;
#pragma unroll
    for (int k = 0; k < 4; k++) {
        int idx = (k & 1) + 2 * tr + (k >> 1) * 128;
        float4 a = row4[idx];
        float x0 = clampA(a.x), x1 = clampA(a.y), x2 = clampA(a.z), x3 = clampA(a.w);
        x[4 * k + 0] = x0; x[4 * k + 1] = x1; x[4 * k + 2] = x2; x[4 * k + 3] = x3;
        mx = fmaxf(mx, fmaxf(fmaxf(x0, x1), fmaxf(x2, x3)));
        am = fmaxf(am, fmaxf(fmaxf(fabsf(x0), fabsf(x1)), fmaxf(fabsf(x2), fabsf(x3))));
    }
#pragma unroll
    for (int o = 16; o > 0; o >>= 1) {
        mx = fmaxf(mx, __shfl_xor_sync(0xFFFFFFFFu, mx, o));
        am = fmaxf(am, __shfl_xor_sync(0xFFFFFFFFu, am, o));
    }

    __shared__ float rm[4][2], ra[4][2], rs[4][2];
    if (lane == 0) { rm[rl][half] = mx; ra[rl][half] = am; }
    __syncthreads();
    mx = fmaxf(rm[rl][0], rm[rl][1]);
    am = fmaxf(fmaxf(ra[rl][0], ra[rl][1]), 1e-30f);

    // quantize
    float invs = 32767.0f / am;
    uint4 w0, w1;
    unsigned int p[8];
#pragma unroll
    for (int t = 0; t < 8; t++) {
        int q0 = (int)rintf(x[2 * t] * invs) + 32768;
        int q1 = (int)rintf(x[2 * t + 1] * invs) + 32768;
        p[t] = (unsigned int)q0 | ((unsigned int)q1 << 16);
    }
    w0.x = p[0]; w0.y = p[1]; w0.z = p[2]; w0.w = p[3];
    w1.x = p[4]; w1.y = p[5]; w1.z = p[6]; w1.w = p[7];
    uint4* __restrict__ q4 = reinterpret_cast<uint4*>(g_q) + r * 128;
    q4[tr] = w0;
    q4[64 + tr] = w1;
    if (tr == 0) g_rs[r] = am / 32767.0f;

    // u1 = LSE (exact values)
    float s = 0.0f;
#pragma unroll
    for (int k = 0; k < 16; k++)
        s += __expf(x[k] - mx);
#pragma unroll
    for (int o = 16; o > 0; o >>= 1)
        s += __shfl_xor_sync(0xFFFFFFFFu, s, o);
    if (lane == 0) rs[rl][half] = s;
    __syncthreads();
    if (tr == 0)
        g_u[r] = mx + __logf(rs[rl][0] + rs[rl][1]);
}

// ---------------------------------------------------------------------------
// Quantized row pass: u[r] = LSE_j( Aq[r][j] - v[j] ).
// ---------------------------------------------------------------------------
__global__ void __launch_bounds__(256) row_lse_q_kernel() {
    int rl   = threadIdx.x >> 6;
    int tr   = threadIdx.x & 63;
    int half = tr >> 5;
    int lane = tr & 31;
    size_t r = (size_t)blockIdx.x * 4 + rl;
    int b = (int)(r >> 10);

    const uint4* __restrict__ q4 = reinterpret_cast<const uint4*>(g_q) + r * 128;
    const float4* __restrict__ v4 = reinterpret_cast<const float4*>(g_v + b * N);

    float s = g_rs[r];
    float C = QBIAS * s;

    uint4 qa = q4[tr];
    uint4 qb = q4[64 + tr];
    float4 v0 = v4[2 * tr];
    float4 v1 = v4[2 * tr + 1];
    float4 v2 = v4[128 + 2 * tr];
    float4 v3 = v4[129 + 2 * tr];

    float x[16];
    unsigned int u[8] = {qa.x, qa.y, qa.z, qa.w, qb.x, qb.y, qb.z, qb.w};
    float vv[16] = {v0.x, v0.y, v0.z, v0.w, v1.x, v1.y, v1.z, v1.w,
                    v2.x, v2.y, v2.z, v2.w, v3.x, v3.y, v3.z, v3.w};
    float mx = -1e30f;
#pragma unroll
    for (int t = 0; t < 8; t++) {
        float flo = __uint_as_float(__byte_perm(u[t], 0x4B000000u, 0x7410));
        float fhi = __uint_as_float(__byte_perm(u[t], 0x4B000000u, 0x7432));
        float x0 = flo * s - (C + vv[2 * t]);
        float x1 = fhi * s - (C + vv[2 * t + 1]);
        x[2 * t] = x0; x[2 * t + 1] = x1;
        mx = fmaxf(mx, fmaxf(x0, x1));
    }
#pragma unroll
    for (int o = 16; o > 0; o >>= 1)
        mx = fmaxf(mx, __shfl_xor_sync(0xFFFFFFFFu, mx, o));

    __shared__ float rm[4][2], rs[4][2];
    if (lane == 0) rm[rl][half] = mx;
    __syncthreads();
    mx = fmaxf(rm[rl][0], rm[rl][1]);

    float sum = 0.0f;
#pragma unroll
    for (int k = 0; k < 16; k++)
        sum += __expf(x[k] - mx);
#pragma unroll
    for (int o = 16; o > 0; o >>= 1)
        sum += __shfl_xor_sync(0xFFFFFFFFu, sum, o);
    if (lane == 0) rs[rl][half] = sum;
    __syncthreads();

    if (tr == 0)
        g_u[r] = mx + __logf(rs[rl][0] + rs[rl][1]);
}

// ---------------------------------------------------------------------------
// Quantized col pass partials. Tile = 128 cols x 128 rows.
// Block (32,16): tx = uint2 (4 cols), ty = row group; rows ty+16k, k<8.
// Grid (N/128, NCHUNK, NB).
// ---------------------------------------------------------------------------
__global__ void __launch_bounds__(512) col_lse_partial_q_kernel() {
    int b  = blockIdx.z;
    int tx = threadIdx.x;           // 0..31
    int ty = threadIdx.y;           // 0..15
    int i0 = blockIdx.y * 128;
    int c4 = blockIdx.x * 32 + tx;  // uint2 index within row (4 cols)

    __shared__ float sw[128];       // QBIAS*s_i + u_i
    __shared__ float ss[128];       // s_i
    __shared__ float4 red[16][33];

    int t = ty * 32 + tx;
    if (t < 128) {
        size_t row = (size_t)b * N + i0 + t;
        float s = g_rs[row];
        ss[t] = s;
        sw[t] = QBIAS * s + g_u[row];
    }
    __syncthreads();

    const uint2* __restrict__ q2 = reinterpret_cast<const uint2*>(g_q);

    float xv[32];
    float4 mx = make_float4(-1e30f, -1e30f, -1e30f, -1e30f);
#pragma unroll
    for (int k = 0; k < 8; k++) {
        int i = ty + 16 * k;
        uint2 q = q2[((size_t)b * N + i0 + i) * 256 + c4];
        float s = ss[i], w = sw[i];
        float f0 = __uint_as_float(__byte_perm(q.x, 0x4B000000u, 0x7410));
        float f1 = __uint_as_float(__byte_perm(q.x, 0x4B000000u, 0x7432));
        float f2 = __uint_as_float(__byte_perm(q.y, 0x4B000000u, 0x7410));
        float f3 = __uint_as_float(__byte_perm(q.y, 0x4B000000u, 0x7432));
        float x0 = f0 * s - w, x1 = f1 * s - w, x2 = f2 * s - w, x3 = f3 * s - w;
        xv[4 * k + 0] = x0; xv[4 * k + 1] = x1; xv[4 * k + 2] = x2; xv[4 * k + 3] = x3;
        mx.x = fmaxf(mx.x, x0); mx.y = fmaxf(mx.y, x1);
        mx.z = fmaxf(mx.z, x2); mx.w = fmaxf(mx.w, x3);
    }

    red[ty][tx] = mx;
    __syncthreads();
    float4 MX = red[0][tx];
#pragma unroll
    for (int k = 1; k < 16; k++) {
        float4 q = red[k][tx];
        MX.x = fmaxf(MX.x, q.x); MX.y = fmaxf(MX.y, q.y);
        MX.z = fmaxf(MX.z, q.z); MX.w = fmaxf(MX.w, q.w);
    }

    float4 sum = make_float4(0.f, 0.f, 0.f, 0.f);
#pragma unroll
    for (int k = 0; k < 8; k++) {
        sum.x += __expf(xv[4 * k + 0] - MX.x);
        sum.y += __expf(xv[4 * k + 1] - MX.y);
        sum.z += __expf(xv[4 * k + 2] - MX.z);
        sum.w += __expf(xv[4 * k + 3] - MX.w);
    }
    __syncthreads();
    red[ty][tx] = sum;
    __syncthreads();

    if (ty == 0) {
        float4 SS = red[0][tx];
#pragma unroll
        for (int k = 1; k < 16; k++) {
            float4 q = red[k][tx];
            SS.x += q.x; SS.y += q.y; SS.z += q.z; SS.w += q.w;
        }
        size_t p = ((size_t)b * NCHUNK + blockIdx.y) * (N / 4) + c4;
        reinterpret_cast<float4*>(g_pm)[p] = MX;
        reinterpret_cast<float4*>(g_ps)[p] = SS;
    }
}

// Merge the NCHUNK partials into v[b][j]. One thread per column.
__global__ void __launch_bounds__(256) col_lse_combine_kernel() {
    int t = blockIdx.x * 256 + threadIdx.x;   // 0..NB*N-1
    int b = t >> 10;
    int j = t & (N - 1);

    size_t pb = (size_t)b * NCHUNK * N + j;
    float m = g_pm[pb];
    float s = g_ps[pb];
#pragma unroll
    for (int c = 1; c < NCHUNK; c++) {
        float pm = g_pm[pb + (size_t)c * N];
        float ps = g_ps[pb + (size_t)c * N];
        float nm = fmaxf(m, pm);
        s = s * __expf(m - nm) + ps * __expf(pm - nm);
        m = nm;
    }
    g_v[t] = m + __logf(s);
}

// ---------------------------------------------------------------------------
// EXACT fp32 row pass (iteration 10).
// ---------------------------------------------------------------------------
__global__ void __launch_bounds__(256) row_lse_kernel(const float* __restrict__ M) {
    int rl   = threadIdx.x >> 6;
    int tr   = threadIdx.x & 63;
    int half = tr >> 5;
    int lane = tr & 31;
    size_t r = (size_t)blockIdx.x * 4 + rl;
    int b = (int)(r >> 10);

    const float4* __restrict__ row4 = reinterpret_cast<const float4*>(M) + r * (N / 4);
    const float4* __restrict__ v4   = reinterpret_cast<const float4*>(g_v + b * N);

    float x[16];
    float mx = -1e30f;
#pragma unroll
    for (int k = 0; k < 4; k++) {
        int idx = tr + 64 * k;
        float4 a = row4[idx];
        float4 v = v4[idx];
        float x0 = clampA(a.x) - v.x;
        float x1 = clampA(a.y) - v.y;
        float x2 = clampA(a.z) - v.z;
        float x3 = clampA(a.w) - v.w;
        x[4 * k + 0] = x0; x[4 * k + 1] = x1;
        x[4 * k + 2] = x2; x[4 * k + 3] = x3;
        mx = fmaxf(mx, fmaxf(fmaxf(x0, x1), fmaxf(x2, x3)));
    }
#pragma unroll
    for (int o = 16; o > 0; o >>= 1)
        mx = fmaxf(mx, __shfl_xor_sync(0xFFFFFFFFu, mx, o));

    __shared__ float rm[4][2], rs[4][2];
    if (lane == 0) rm[rl][half] = mx;
    __syncthreads();
    mx = fmaxf(rm[rl][0], rm[rl][1]);

    float s = 0.0f;
#pragma unroll
    for (int k = 0; k < 16; k++)
        s += __expf(x[k] - mx);
#pragma unroll
    for (int o = 16; o > 0; o >>= 1)
        s += __shfl_xor_sync(0xFFFFFFFFu, s, o);
    if (lane == 0) rs[rl][half] = s;
    __syncthreads();

    if (tr == 0)
        g_u[r] = mx + __logf(rs[rl][0] + rs[rl][1]);
}

// ---------------------------------------------------------------------------
// EXACT last col pass fused with output write (iteration 10 col + exp).
// ---------------------------------------------------------------------------
__global__ void __launch_bounds__(1024) col_lse_finalize_kernel(const float* __restrict__ M,
                                                                float* __restrict__ out) {
    int b = blockIdx.y;
    int cx = threadIdx.x;
    int y  = threadIdx.y;
    int j = blockIdx.x * 32 + cx;

    __shared__ float us[N];
    __shared__ float sm_m[32][33];
    __shared__ float sm_s[32][33];

    us[y * 32 + cx] = g_u[b * N + y * 32 + cx];
    __syncthreads();

    const float* __restrict__ base = M + (size_t)b * N * N + j;

    float xv[32];
    float mx = -1e30f;
#pragma unroll
    for (int k = 0; k < 32; k++) {
        int i = y + 32 * k;
        float a = base[(size_t)i * N];
        float t = clampA(a) - us[i];
        xv[k] = t;
        mx = fmaxf(mx, t);
    }

    sm_m[y][cx] = mx;
    __syncthreads();

    float MX = sm_m[0][cx];
#pragma unroll
    for (int k = 1; k < 32; k++)
        MX = fmaxf(MX, sm_m[k][cx]);

    float s = 0.0f;
#pragma unroll
    for (int k = 0; k < 32; k++)
        s += __expf(xv[k] - MX);

    sm_s[y][cx] = s;
    __syncthreads();

    float SS = sm_s[0][cx];
#pragma unroll
    for (int k = 1; k < 32; k++)
        SS += sm_s[k][cx];
    float V = MX + __logf(SS);

    float* __restrict__ obase = out + (size_t)b * N * N + j;
#pragma unroll
    for (int k = 0; k < 32; k++) {
        int i = y + 32 * k;
        obase[(size_t)i * N] = __expf(xv[k] - V);
    }
}

extern "C" void kernel_launch(void* const* d_in, const int* in_sizes, int n_in,
                              void* d_out, int out_size) {
    const float* M = (const float*)d_in[0];
    float* out = (float*)d_out;

    // Quantize + row pass 1 (exact)
    quant_row1_kernel<<<(NB * N) / 4, 256>>>(M);

    // Iterations 1..9: quantized col pass, quantized row pass (2..9)
    for (int it = 0; it < ITERS - 1; it++) {
        col_lse_partial_q_kernel<<<dim3(N / 128, NCHUNK, NB), dim3(32, 16)>>>();
        col_lse_combine_kernel<<<(NB * N) / 256, 256>>>();
        if (it < ITERS - 2)
            row_lse_q_kernel<<<(NB * N) / 4, 256>>>();
    }

    // Iteration 10: exact row pass, exact fused col + finalize
    row_lse_kernel<<<(NB * N) / 4, 256>>>(M);
    col_lse_finalize_kernel<<<dim3(N / 32, NB), dim3(32, 32)>>>(M, out);
}

// round 7
// speedup vs baseline: 1.2848x; 1.2848x over previous
#include <cuda_runtime.h>
#include <math.h>

#define NB 64
#define N 1024
#define ITERS 10
#define NCHUNK 16

// Scratch (allocation-free, static device memory)
__device__ __align__(16) float g_u[NB * N];
__device__ __align__(16) float g_v[NB * N];
__device__ __align__(16) float g_pm[NB * NCHUNK * N];
__device__ __align__(16) float g_ps[NB * NCHUNK * N];
// Quantized A (biased uint16) + per-row quant scale
__device__ __align__(16) unsigned short g_q[(size_t)NB * N * N];
__device__ __align__(16) float g_rs[NB * N];

// Dequant: A = as_float(0x4B000000 | u16) * s - 8421376 * s
#define QBIAS 8421376.0f   // 2^23 + 32768

__device__ __forceinline__ float clampA(float m) {
    return fminf(fmaxf(m, -25.0f), 25.0f) * 10.0f;   // clip(M,±25)/0.1
}

// ---------------------------------------------------------------------------
// Quantize A to biased uint16 with per-row scale; ALSO computes
// u1[r] = LSE_j(A[r][j]) (first row pass, v0 = 0) from exact values.
// Block 256 = 4 rows x 64 threads.
// ---------------------------------------------------------------------------
__global__ void __launch_bounds__(256, 2) quant_row1_kernel(const float* __restrict__ M) {
    int rl   = threadIdx.x >> 6;
    int tr   = threadIdx.x & 63;
    int half = tr >> 5;
    int lane = tr & 31;
    size_t r = (size_t)blockIdx.x * 4 + rl;

    const float4* __restrict__ row4 = reinterpret_cast<const float4*>(M) + r * (N / 4);

    float x[16];
    float mx = -1e30f, am = 0.0f;
#pragma unroll
    for (int k = 0; k < 4; k++) {
        int idx = (k & 1) + 2 * tr + (k >> 1) * 128;
        float4 a = row4[idx];
        float x0 = clampA(a.x), x1 = clampA(a.y), x2 = clampA(a.z), x3 = clampA(a.w);
        x[4 * k + 0] = x0; x[4 * k + 1] = x1; x[4 * k + 2] = x2; x[4 * k + 3] = x3;
        mx = fmaxf(mx, fmaxf(fmaxf(x0, x1), fmaxf(x2, x3)));
        am = fmaxf(am, fmaxf(fmaxf(fabsf(x0), fabsf(x1)), fmaxf(fabsf(x2), fabsf(x3))));
    }
#pragma unroll
    for (int o = 16; o > 0; o >>= 1) {
        mx = fmaxf(mx, __shfl_xor_sync(0xFFFFFFFFu, mx, o));
        am = fmaxf(am, __shfl_xor_sync(0xFFFFFFFFu, am, o));
    }

    __shared__ float rm[4][2], ra[4][2], rs[4][2];
    if (lane == 0) { rm[rl][half] = mx; ra[rl][half] = am; }
    __syncthreads();
    mx = fmaxf(rm[rl][0], rm[rl][1]);
    am = fmaxf(fmaxf(ra[rl][0], ra[rl][1]), 1e-30f);

    // quantize
    float invs = 32767.0f / am;
    uint4 w;
    uint4* __restrict__ q4 = reinterpret_cast<uint4*>(g_q) + r * 128;
#pragma unroll
    for (int t = 0; t < 4; t++) {
        unsigned int q0 = (unsigned int)((int)rintf(x[2 * t] * invs) + 32768);
        unsigned int q1 = (unsigned int)((int)rintf(x[2 * t + 1] * invs) + 32768);
        (&w.x)[t] = q0 | (q1 << 16);
    }
    q4[tr] = w;
#pragma unroll
    for (int t = 0; t < 4; t++) {
        unsigned int q0 = (unsigned int)((int)rintf(x[8 + 2 * t] * invs) + 32768);
        unsigned int q1 = (unsigned int)((int)rintf(x[9 + 2 * t] * invs) + 32768);
        (&w.x)[t] = q0 | (q1 << 16);
    }
    q4[64 + tr] = w;
    if (tr == 0) g_rs[r] = am / 32767.0f;

    // u1 = LSE (exact values)
    float s = 0.0f;
#pragma unroll
    for (int k = 0; k < 16; k++)
        s += __expf(x[k] - mx);
#pragma unroll
    for (int o = 16; o > 0; o >>= 1)
        s += __shfl_xor_sync(0xFFFFFFFFu, s, o);
    if (lane == 0) rs[rl][half] = s;
    __syncthreads();
    if (tr == 0)
        g_u[r] = mx + __logf(rs[rl][0] + rs[rl][1]);
}

// ---------------------------------------------------------------------------
// Quantized row pass: u[r] = LSE_j( Aq[r][j] - v[j] ).
// Inline consumption of packed words and v (only x[16] persists in regs).
// ---------------------------------------------------------------------------
__global__ void __launch_bounds__(256, 2) row_lse_q_kernel() {
    int rl   = threadIdx.x >> 6;
    int tr   = threadIdx.x & 63;
    int half = tr >> 5;
    int lane = tr & 31;
    size_t r = (size_t)blockIdx.x * 4 + rl;
    int b = (int)(r >> 10);

    const uint4* __restrict__ q4 = reinterpret_cast<const uint4*>(g_q) + r * 128;
    const float4* __restrict__ v4 = reinterpret_cast<const float4*>(g_v + b * N);

    float s = g_rs[r];
    float C = QBIAS * s;

    float x[16];
    float mx = -1e30f;

    {
        uint4 q = q4[tr];
        float4 va = v4[2 * tr];
        float4 vb = v4[2 * tr + 1];
        float f;
        f = __uint_as_float(__byte_perm(q.x, 0x4B000000u, 0x7410)); x[0] = f * s - (C + va.x);
        f = __uint_as_float(__byte_perm(q.x, 0x4B000000u, 0x7432)); x[1] = f * s - (C + va.y);
        f = __uint_as_float(__byte_perm(q.y, 0x4B000000u, 0x7410)); x[2] = f * s - (C + va.z);
        f = __uint_as_float(__byte_perm(q.y, 0x4B000000u, 0x7432)); x[3] = f * s - (C + va.w);
        f = __uint_as_float(__byte_perm(q.z, 0x4B000000u, 0x7410)); x[4] = f * s - (C + vb.x);
        f = __uint_as_float(__byte_perm(q.z, 0x4B000000u, 0x7432)); x[5] = f * s - (C + vb.y);
        f = __uint_as_float(__byte_perm(q.w, 0x4B000000u, 0x7410)); x[6] = f * s - (C + vb.z);
        f = __uint_as_float(__byte_perm(q.w, 0x4B000000u, 0x7432)); x[7] = f * s - (C + vb.w);
    }
    {
        uint4 q = q4[64 + tr];
        float4 va = v4[128 + 2 * tr];
        float4 vb = v4[129 + 2 * tr];
        float f;
        f = __uint_as_float(__byte_perm(q.x, 0x4B000000u, 0x7410)); x[8]  = f * s - (C + va.x);
        f = __uint_as_float(__byte_perm(q.x, 0x4B000000u, 0x7432)); x[9]  = f * s - (C + va.y);
        f = __uint_as_float(__byte_perm(q.y, 0x4B000000u, 0x7410)); x[10] = f * s - (C + va.z);
        f = __uint_as_float(__byte_perm(q.y, 0x4B000000u, 0x7432)); x[11] = f * s - (C + va.w);
        f = __uint_as_float(__byte_perm(q.z, 0x4B000000u, 0x7410)); x[12] = f * s - (C + vb.x);
        f = __uint_as_float(__byte_perm(q.z, 0x4B000000u, 0x7432)); x[13] = f * s - (C + vb.y);
        f = __uint_as_float(__byte_perm(q.w, 0x4B000000u, 0x7410)); x[14] = f * s - (C + vb.z);
        f = __uint_as_float(__byte_perm(q.w, 0x4B000000u, 0x7432)); x[15] = f * s - (C + vb.w);
    }
#pragma unroll
    for (int k = 0; k < 16; k++)
        mx = fmaxf(mx, x[k]);
#pragma unroll
    for (int o = 16; o > 0; o >>= 1)
        mx = fmaxf(mx, __shfl_xor_sync(0xFFFFFFFFu, mx, o));

    __shared__ float rm[4][2], rsum[4][2];
    if (lane == 0) rm[rl][half] = mx;
    __syncthreads();
    mx = fmaxf(rm[rl][0], rm[rl][1]);

    float sum = 0.0f;
#pragma unroll
    for (int k = 0; k < 16; k++)
        sum += __expf(x[k] - mx);
#pragma unroll
    for (int o = 16; o > 0; o >>= 1)
        sum += __shfl_xor_sync(0xFFFFFFFFu, sum, o);
    if (lane == 0) rsum[rl][half] = sum;
    __syncthreads();

    if (tr == 0)
        g_u[r] = mx + __logf(rsum[rl][0] + rsum[rl][1]);
}

// ---------------------------------------------------------------------------
// Quantized col pass partials. Tile = 128 cols x 64 rows.
// Block (64,8) = 512 threads: tx = u32 word (2 cols), ty = row group;
// thread covers rows ty+8k (k<8) -> xv[16]. Grid (N/128, NCHUNK, NB).
// ---------------------------------------------------------------------------
__global__ void __launch_bounds__(512, 2) col_lse_partial_q_kernel() {
    int b  = blockIdx.z;
    int tx = threadIdx.x;           // 0..63
    int ty = threadIdx.y;           // 0..7
    int i0 = blockIdx.y * 64;
    int c2 = blockIdx.x * 64 + tx;  // u32 word index within row (2 cols)

    __shared__ float sw[64];        // QBIAS*s_i + u_i
    __shared__ float ss[64];        // s_i
    __shared__ float red0[8][65];
    __shared__ float red1[8][65];

    int t = ty * 64 + tx;
    if (t < 64) {
        size_t row = (size_t)b * N + i0 + t;
        float s = g_rs[row];
        ss[t] = s;
        sw[t] = QBIAS * s + g_u[row];
    }
    __syncthreads();

    const unsigned int* __restrict__ qw = reinterpret_cast<const unsigned int*>(g_q);

    float xv[16];
    float m0 = -1e30f, m1 = -1e30f;
#pragma unroll
    for (int k = 0; k < 8; k++) {
        int i = ty + 8 * k;
        unsigned int q = qw[((size_t)b * N + i0 + i) * 512 + c2];
        float s = ss[i], w = sw[i];
        float x0 = __uint_as_float(__byte_perm(q, 0x4B000000u, 0x7410)) * s - w;
        float x1 = __uint_as_float(__byte_perm(q, 0x4B000000u, 0x7432)) * s - w;
        xv[2 * k]     = x0;
        xv[2 * k + 1] = x1;
        m0 = fmaxf(m0, x0);
        m1 = fmaxf(m1, x1);
    }

    red0[ty][tx] = m0;
    red1[ty][tx] = m1;
    __syncthreads();
    float M0 = red0[0][tx], M1 = red1[0][tx];
#pragma unroll
    for (int k = 1; k < 8; k++) {
        M0 = fmaxf(M0, red0[k][tx]);
        M1 = fmaxf(M1, red1[k][tx]);
    }

    float s0 = 0.0f, s1 = 0.0f;
#pragma unroll
    for (int k = 0; k < 8; k++) {
        s0 += __expf(xv[2 * k]     - M0);
        s1 += __expf(xv[2 * k + 1] - M1);
    }
    __syncthreads();
    red0[ty][tx] = s0;
    red1[ty][tx] = s1;
    __syncthreads();

    if (ty == 0) {
        float S0 = red0[0][tx], S1 = red1[0][tx];
#pragma unroll
        for (int k = 1; k < 8; k++) {
            S0 += red0[k][tx];
            S1 += red1[k][tx];
        }
        size_t p = ((size_t)b * NCHUNK + blockIdx.y) * (N / 2) + c2;
        reinterpret_cast<float2*>(g_pm)[p] = make_float2(M0, M1);
        reinterpret_cast<float2*>(g_ps)[p] = make_float2(S0, S1);
    }
}

// Merge the NCHUNK partials into v[b][j]. One thread per column.
__global__ void __launch_bounds__(256) col_lse_combine_kernel() {
    int t = blockIdx.x * 256 + threadIdx.x;   // 0..NB*N-1
    int b = t >> 10;
    int j = t & (N - 1);

    size_t pb = (size_t)b * NCHUNK * N + j;
    float m = g_pm[pb];
    float s = g_ps[pb];
#pragma unroll
    for (int c = 1; c < NCHUNK; c++) {
        float pm = g_pm[pb + (size_t)c * N];
        float ps = g_ps[pb + (size_t)c * N];
        float nm = fmaxf(m, pm);
        s = s * __expf(m - nm) + ps * __expf(pm - nm);
        m = nm;
    }
    g_v[t] = m + __logf(s);
}

// ---------------------------------------------------------------------------
// EXACT fp32 row pass (iteration 10).
// ---------------------------------------------------------------------------
__global__ void __launch_bounds__(256, 2) row_lse_kernel(const float* __restrict__ M) {
    int rl   = threadIdx.x >> 6;
    int tr   = threadIdx.x & 63;
    int half = tr >> 5;
    int lane = tr & 31;
    size_t r = (size_t)blockIdx.x * 4 + rl;
    int b = (int)(r >> 10);

    const float4* __restrict__ row4 = reinterpret_cast<const float4*>(M) + r * (N / 4);
    const float4* __restrict__ v4   = reinterpret_cast<const float4*>(g_v + b * N);

    float x[16];
    float mx = -1e30f;
#pragma unroll
    for (int k = 0; k < 4; k++) {
        int idx = tr + 64 * k;
        float4 a = row4[idx];
        float4 v = v4[idx];
        float x0 = clampA(a.x) - v.x;
        float x1 = clampA(a.y) - v.y;
        float x2 = clampA(a.z) - v.z;
        float x3 = clampA(a.w) - v.w;
        x[4 * k + 0] = x0; x[4 * k + 1] = x1;
        x[4 * k + 2] = x2; x[4 * k + 3] = x3;
        mx = fmaxf(mx, fmaxf(fmaxf(x0, x1), fmaxf(x2, x3)));
    }
#pragma unroll
    for (int o = 16; o > 0; o >>= 1)
        mx = fmaxf(mx, __shfl_xor_sync(0xFFFFFFFFu, mx, o));

    __shared__ float rm[4][2], rs[4][2];
    if (lane == 0) rm[rl][half] = mx;
    __syncthreads();
    mx = fmaxf(rm[rl][0], rm[rl][1]);

    float s = 0.0f;
#pragma unroll
    for (int k = 0; k < 16; k++)
        s += __expf(x[k] - mx);
#pragma unroll
    for (int o = 16; o > 0; o >>= 1)
        s += __shfl_xor_sync(0xFFFFFFFFu, s, o);
    if (lane == 0) rs[rl][half] = s;
    __syncthreads();

    if (tr == 0)
        g_u[r] = mx + __logf(rs[rl][0] + rs[rl][1]);
}

// ---------------------------------------------------------------------------
// EXACT last col pass fused with output write (iteration 10 col + exp).
// ---------------------------------------------------------------------------
__global__ void __launch_bounds__(1024) col_lse_finalize_kernel(const float* __restrict__ M,
                                                                float* __restrict__ out) {
    int b = blockIdx.y;
    int cx = threadIdx.x;
    int y  = threadIdx.y;
    int j = blockIdx.x * 32 + cx;

    __shared__ float us[N];
    __shared__ float sm_m[32][33];
    __shared__ float sm_s[32][33];

    us[y * 32 + cx] = g_u[b * N + y * 32 + cx];
    __syncthreads();

    const float* __restrict__ base = M + (size_t)b * N * N + j;

    float xv[32];
    float mx = -1e30f;
#pragma unroll
    for (int k = 0; k < 32; k++) {
        int i = y + 32 * k;
        float a = base[(size_t)i * N];
        float t = clampA(a) - us[i];
        xv[k] = t;
        mx = fmaxf(mx, t);
    }

    sm_m[y][cx] = mx;
    __syncthreads();

    float MX = sm_m[0][cx];
#pragma unroll
    for (int k = 1; k < 32; k++)
        MX = fmaxf(MX, sm_m[k][cx]);

    float s = 0.0f;
#pragma unroll
    for (int k = 0; k < 32; k++)
        s += __expf(xv[k] - MX);

    sm_s[y][cx] = s;
    __syncthreads();

    float SS = sm_s[0][cx];
#pragma unroll
    for (int k = 1; k < 32; k++)
        SS += sm_s[k][cx];
    float V = MX + __logf(SS);

    float* __restrict__ obase = out + (size_t)b * N * N + j;
#pragma unroll
    for (int k = 0; k < 32; k++) {
        int i = y + 32 * k;
        obase[(size_t)i * N] = __expf(xv[k] - V);
    }
}

extern "C" void kernel_launch(void* const* d_in, const int* in_sizes, int n_in,
                              void* d_out, int out_size) {
    const float* M = (const float*)d_in[0];
    float* out = (float*)d_out;

    // Quantize + row pass 1 (exact)
    quant_row1_kernel<<<(NB * N) / 4, 256>>>(M);

    // Iterations 1..9: quantized col pass + combine, quantized row pass (2..9)
    for (int it = 0; it < ITERS - 1; it++) {
        col_lse_partial_q_kernel<<<dim3(N / 128, NCHUNK, NB), dim3(64, 8)>>>();
        col_lse_combine_kernel<<<(NB * N) / 256, 256>>>();
        if (it < ITERS - 2)
            row_lse_q_kernel<<<(NB * N) / 4, 256>>>();
    }

    // Iteration 10: exact row pass, exact fused col + finalize
    row_lse_kernel<<<(NB * N) / 4, 256>>>(M);
    col_lse_finalize_kernel<<<dim3(N / 32, NB), dim3(32, 32)>>>(M, out);
}

// round 8
// speedup vs baseline: 1.8830x; 1.4655x over previous
#include <cuda_runtime.h>
#include <cuda_bf16.h>
#include <math.h>

#define NB 64
#define N 1024
#define ITERS 10
#define NCHUNK 8

// Scratch (allocation-free, static device memory)
__device__ __align__(16) float g_u[NB * N];     // log-domain row potential
__device__ __align__(16) float g_v[NB * N];     // log-domain col potential (for exact passes)
__device__ __align__(16) float g_r[NB * N];     // exp-domain row scaling
__device__ __align__(16) float g_c[NB * N];     // exp-domain col scaling
__device__ __align__(16) float g_ps[NB * NCHUNK * N];   // col partial sums
// K = exp(A - u1) stored as bf16
__device__ __align__(16) unsigned short g_q[(size_t)NB * N * N];

__device__ __forceinline__ float clampA(float m) {
    return fminf(fmaxf(m, -25.0f), 25.0f) * 10.0f;   // clip(M,±25)/0.1
}
// bf16 pair decode (lo = bits[0:16), hi = bits[16:32))
__device__ __forceinline__ float blo(unsigned int w) { return __uint_as_float(w << 16); }
__device__ __forceinline__ float bhi(unsigned int w) { return __uint_as_float(w & 0xFFFF0000u); }
__device__ __forceinline__ unsigned int packbf(float lo, float hi) {
    __nv_bfloat162 h = __floats2bfloat162_rn(lo, hi);
    return *reinterpret_cast<unsigned int*>(&h);
}

__global__ void init_r_kernel() {
    int t = blockIdx.x * blockDim.x + threadIdx.x;
    if (t < NB * N) g_r[t] = 1.0f;
}

// ---------------------------------------------------------------------------
// Pass 0: exact row-LSE (u1) + write K = exp(A - u1) in bf16.
// Block 256 = 4 rows x 64 threads; thread covers cols [8tr,8tr+8) and [512+8tr,+8).
// ---------------------------------------------------------------------------
__global__ void __launch_bounds__(256, 2) exp_quant_kernel(const float* __restrict__ M) {
    int rl   = threadIdx.x >> 6;
    int tr   = threadIdx.x & 63;
    int half = tr >> 5;
    int lane = tr & 31;
    size_t r = (size_t)blockIdx.x * 4 + rl;

    const float4* __restrict__ row4 = reinterpret_cast<const float4*>(M) + r * (N / 4);

    float x[16];
    float mx = -1e30f;
#pragma unroll
    for (int k = 0; k < 4; k++) {
        int idx = (k & 1) + 2 * tr + (k >> 1) * 128;
        float4 a = row4[idx];
        float x0 = clampA(a.x), x1 = clampA(a.y), x2 = clampA(a.z), x3 = clampA(a.w);
        x[4 * k + 0] = x0; x[4 * k + 1] = x1; x[4 * k + 2] = x2; x[4 * k + 3] = x3;
        mx = fmaxf(mx, fmaxf(fmaxf(x0, x1), fmaxf(x2, x3)));
    }
#pragma unroll
    for (int o = 16; o > 0; o >>= 1)
        mx = fmaxf(mx, __shfl_xor_sync(0xFFFFFFFFu, mx, o));

    __shared__ float rm[4][2], rs[4][2];
    if (lane == 0) rm[rl][half] = mx;
    __syncthreads();
    mx = fmaxf(rm[rl][0], rm[rl][1]);

    // exp in place, partial sum
    float s = 0.0f;
#pragma unroll
    for (int k = 0; k < 16; k++) {
        x[k] = __expf(x[k] - mx);
        s += x[k];
    }
#pragma unroll
    for (int o = 16; o > 0; o >>= 1)
        s += __shfl_xor_sync(0xFFFFFFFFu, s, o);
    if (lane == 0) rs[rl][half] = s;
    __syncthreads();
    float S = rs[rl][0] + rs[rl][1];
    float inv = 1.0f / S;

    // K = exp(x - u1) = exp(x-mx)/S, bf16 packed
    uint4 w;
    uint4* __restrict__ q4 = reinterpret_cast<uint4*>(g_q) + r * 128;
    w.x = packbf(x[0] * inv, x[1] * inv);
    w.y = packbf(x[2] * inv, x[3] * inv);
    w.z = packbf(x[4] * inv, x[5] * inv);
    w.w = packbf(x[6] * inv, x[7] * inv);
    q4[tr] = w;
    w.x = packbf(x[8] * inv, x[9] * inv);
    w.y = packbf(x[10] * inv, x[11] * inv);
    w.z = packbf(x[12] * inv, x[13] * inv);
    w.w = packbf(x[14] * inv, x[15] * inv);
    q4[64 + tr] = w;

    if (tr == 0)
        g_u[r] = mx + __logf(S);
}

// ---------------------------------------------------------------------------
// Exp-domain row pass: r_i = 1 / Sum_j K_ij * c_j. No exp at all.
// Block 256 = 4 rows x 64 threads; 2 uint4 K loads + 4 float4 c loads per thread.
// ---------------------------------------------------------------------------
__global__ void __launch_bounds__(256) row_dot_kernel() {
    int rl   = threadIdx.x >> 6;
    int tr   = threadIdx.x & 63;
    int half = tr >> 5;
    int lane = tr & 31;
    size_t r = (size_t)blockIdx.x * 4 + rl;
    int b = (int)(r >> 10);

    const uint4* __restrict__ q4 = reinterpret_cast<const uint4*>(g_q) + r * 128;
    const float4* __restrict__ c4 = reinterpret_cast<const float4*>(g_c + b * N);

    float sum = 0.0f;
    {
        uint4 q = q4[tr];
        float4 ca = c4[2 * tr];
        float4 cb = c4[2 * tr + 1];
        sum += blo(q.x) * ca.x + bhi(q.x) * ca.y;
        sum += blo(q.y) * ca.z + bhi(q.y) * ca.w;
        sum += blo(q.z) * cb.x + bhi(q.z) * cb.y;
        sum += blo(q.w) * cb.z + bhi(q.w) * cb.w;
    }
    {
        uint4 q = q4[64 + tr];
        float4 ca = c4[128 + 2 * tr];
        float4 cb = c4[129 + 2 * tr];
        sum += blo(q.x) * ca.x + bhi(q.x) * ca.y;
        sum += blo(q.y) * ca.z + bhi(q.y) * ca.w;
        sum += blo(q.z) * cb.x + bhi(q.z) * cb.y;
        sum += blo(q.w) * cb.z + bhi(q.w) * cb.w;
    }
#pragma unroll
    for (int o = 16; o > 0; o >>= 1)
        sum += __shfl_xor_sync(0xFFFFFFFFu, sum, o);

    __shared__ float rs[4][2];
    if (lane == 0) rs[rl][half] = sum;
    __syncthreads();

    if (tr == 0) {
        float S = fmaxf(rs[rl][0] + rs[rl][1], 1e-30f);
        g_r[r] = 1.0f / S;
    }
}

// ---------------------------------------------------------------------------
// Exp-domain col pass partials: S_j = Sum_i K_ij * r_i over a 128-row chunk.
// Block (64,8)=512: tx = uint4 col-word (8 cols), ty = row group (rows ty+8k, k<16).
// Per thread: 16 uint4 loads (256B DRAM), 8 fp32 accumulators.
// Grid (2, NCHUNK, NB).
// ---------------------------------------------------------------------------
__global__ void __launch_bounds__(512, 2) col_sum_kernel() {
    int b  = blockIdx.z;
    int tx = threadIdx.x;           // 0..63
    int ty = threadIdx.y;           // 0..7
    int i0 = blockIdx.y * 128;
    int c  = blockIdx.x * 64 + tx;  // uint4 index within row [0,128)

    __shared__ float sr[128];
    __shared__ float red[8][512];

    int t = ty * 64 + tx;
    if (t < 128)
        sr[t] = g_r[b * N + i0 + t];
    __syncthreads();

    const uint4* __restrict__ q4 = reinterpret_cast<const uint4*>(g_q);

    float acc[8] = {0.f, 0.f, 0.f, 0.f, 0.f, 0.f, 0.f, 0.f};
#pragma unroll
    for (int k = 0; k < 16; k++) {
        int i = ty + 8 * k;
        uint4 q = q4[((size_t)b * N + i0 + i) * 128 + c];
        float rr = sr[i];
        acc[0] += blo(q.x) * rr; acc[1] += bhi(q.x) * rr;
        acc[2] += blo(q.y) * rr; acc[3] += bhi(q.y) * rr;
        acc[4] += blo(q.z) * rr; acc[5] += bhi(q.z) * rr;
        acc[6] += blo(q.w) * rr; acc[7] += bhi(q.w) * rr;
    }

    // red[ty][q*64+tx] = acc[q]: per-q writes conflict-free
#pragma unroll
    for (int q = 0; q < 8; q++)
        red[ty][q * 64 + tx] = acc[q];
    __syncthreads();

    // Thread t reduces position t across ty: column = (t&63)*8 + (t>>6) = tx*8 + ty
    float S = red[0][t];
#pragma unroll
    for (int k = 1; k < 8; k++)
        S += red[k][t];
    int j = blockIdx.x * 512 + tx * 8 + ty;
    g_ps[((size_t)b * NCHUNK + blockIdx.y) * N + j] = S;
}

// Merge NCHUNK partials: c_j = 1/S_j, v_j = log S_j.
__global__ void __launch_bounds__(256) combine_kernel() {
    int t = blockIdx.x * 256 + threadIdx.x;   // 0..NB*N-1
    int b = t >> 10;
    int j = t & (N - 1);

    size_t pb = (size_t)b * NCHUNK * N + j;
    float S = g_ps[pb];
#pragma unroll
    for (int cc = 1; cc < NCHUNK; cc++)
        S += g_ps[pb + (size_t)cc * N];
    S = fmaxf(S, 1e-30f);
    g_c[t] = 1.0f / S;
    g_v[t] = __logf(S);
}

// ---------------------------------------------------------------------------
// EXACT fp32 row pass (iteration 10): u = LSE_j(A - v).
// ---------------------------------------------------------------------------
__global__ void __launch_bounds__(256, 2) row_lse_kernel(const float* __restrict__ M) {
    int rl   = threadIdx.x >> 6;
    int tr   = threadIdx.x & 63;
    int half = tr >> 5;
    int lane = tr & 31;
    size_t r = (size_t)blockIdx.x * 4 + rl;
    int b = (int)(r >> 10);

    const float4* __restrict__ row4 = reinterpret_cast<const float4*>(M) + r * (N / 4);
    const float4* __restrict__ v4   = reinterpret_cast<const float4*>(g_v + b * N);

    float x[16];
    float mx = -1e30f;
#pragma unroll
    for (int k = 0; k < 4; k++) {
        int idx = tr + 64 * k;
        float4 a = row4[idx];
        float4 v = v4[idx];
        float x0 = clampA(a.x) - v.x;
        float x1 = clampA(a.y) - v.y;
        float x2 = clampA(a.z) - v.z;
        float x3 = clampA(a.w) - v.w;
        x[4 * k + 0] = x0; x[4 * k + 1] = x1;
        x[4 * k + 2] = x2; x[4 * k + 3] = x3;
        mx = fmaxf(mx, fmaxf(fmaxf(x0, x1), fmaxf(x2, x3)));
    }
#pragma unroll
    for (int o = 16; o > 0; o >>= 1)
        mx = fmaxf(mx, __shfl_xor_sync(0xFFFFFFFFu, mx, o));

    __shared__ float rm[4][2], rs[4][2];
    if (lane == 0) rm[rl][half] = mx;
    __syncthreads();
    mx = fmaxf(rm[rl][0], rm[rl][1]);

    float s = 0.0f;
#pragma unroll
    for (int k = 0; k < 16; k++)
        s += __expf(x[k] - mx);
#pragma unroll
    for (int o = 16; o > 0; o >>= 1)
        s += __shfl_xor_sync(0xFFFFFFFFu, s, o);
    if (lane == 0) rs[rl][half] = s;
    __syncthreads();

    if (tr == 0)
        g_u[r] = mx + __logf(rs[rl][0] + rs[rl][1]);
}

// ---------------------------------------------------------------------------
// EXACT last col pass fused with output write (iteration 10 col + exp).
// ---------------------------------------------------------------------------
__global__ void __launch_bounds__(1024) col_lse_finalize_kernel(const float* __restrict__ M,
                                                                float* __restrict__ out) {
    int b = blockIdx.y;
    int cx = threadIdx.x;
    int y  = threadIdx.y;
    int j = blockIdx.x * 32 + cx;

    __shared__ float us[N];
    __shared__ float sm_m[32][33];
    __shared__ float sm_s[32][33];

    us[y * 32 + cx] = g_u[b * N + y * 32 + cx];
    __syncthreads();

    const float* __restrict__ base = M + (size_t)b * N * N + j;

    float xv[32];
    float mx = -1e30f;
#pragma unroll
    for (int k = 0; k < 32; k++) {
        int i = y + 32 * k;
        float a = base[(size_t)i * N];
        float t = clampA(a) - us[i];
        xv[k] = t;
        mx = fmaxf(mx, t);
    }

    sm_m[y][cx] = mx;
    __syncthreads();

    float MX = sm_m[0][cx];
#pragma unroll
    for (int k = 1; k < 32; k++)
        MX = fmaxf(MX, sm_m[k][cx]);

    float s = 0.0f;
#pragma unroll
    for (int k = 0; k < 32; k++)
        s += __expf(xv[k] - MX);

    sm_s[y][cx] = s;
    __syncthreads();

    float SS = sm_s[0][cx];
#pragma unroll
    for (int k = 1; k < 32; k++)
        SS += sm_s[k][cx];
    float V = MX + __logf(SS);

    float* __restrict__ obase = out + (size_t)b * N * N + j;
#pragma unroll
    for (int k = 0; k < 32; k++) {
        int i = y + 32 * k;
        obase[(size_t)i * N] = __expf(xv[k] - V);
    }
}

extern "C" void kernel_launch(void* const* d_in, const int* in_sizes, int n_in,
                              void* d_out, int out_size) {
    const float* M = (const float*)d_in[0];
    float* out = (float*)d_out;

    init_r_kernel<<<(NB * N + 255) / 256, 256>>>();
    // Iteration 1 row pass (exact) + K = exp(A - u1) in bf16
    exp_quant_kernel<<<(NB * N) / 4, 256>>>(M);

    // Iterations 1..9 col passes + iterations 2..9 row passes (exp domain)
    for (int it = 0; it < ITERS - 1; it++) {
        col_sum_kernel<<<dim3(2, NCHUNK, NB), dim3(64, 8)>>>();
        combine_kernel<<<(NB * N) / 256, 256>>>();
        if (it < ITERS - 2)
            row_dot_kernel<<<(NB * N) / 4, 256>>>();
    }

    // Iteration 10: exact row pass, exact fused col + finalize
    row_lse_kernel<<<(NB * N) / 4, 256>>>(M);
    col_lse_finalize_kernel<<<dim3(N / 32, NB), dim3(32, 32)>>>(M, out);
}

// round 9
// speedup vs baseline: 1.9220x; 1.0207x over previous
#include <cuda_runtime.h>
#include <cuda_bf16.h>
#include <math.h>

#define NB 64
#define N 1024
#define ITERS 10
#define NCHUNK 8

// Scratch (allocation-free, static device memory)
__device__ __align__(16) float g_u[NB * N];     // u1, later u10 (log-domain row potential)
__device__ __align__(16) float g_v[NB * N];     // log-domain col potential
__device__ __align__(16) float g_r[NB * N];     // exp-domain row scaling
__device__ __align__(16) float g_c[NB * N];     // exp-domain col scaling
__device__ __align__(16) float g_ps[NB * NCHUNK * N];   // col partial sums
// K = exp(A - u1) stored as bf16
__device__ __align__(16) unsigned short g_q[(size_t)NB * N * N];

__device__ __forceinline__ float clampA(float m) {
    return fminf(fmaxf(m, -25.0f), 25.0f) * 10.0f;   // clip(M,±25)/0.1
}
// bf16 pair decode (lo = bits[0:16), hi = bits[16:32))
__device__ __forceinline__ float blo(unsigned int w) { return __uint_as_float(w << 16); }
__device__ __forceinline__ float bhi(unsigned int w) { return __uint_as_float(w & 0xFFFF0000u); }
__device__ __forceinline__ unsigned int packbf(float lo, float hi) {
    __nv_bfloat162 h = __floats2bfloat162_rn(lo, hi);
    return *reinterpret_cast<unsigned int*>(&h);
}

// ---------------------------------------------------------------------------
// Pass 0: exact row-LSE (u1) + write K = exp(A - u1) in bf16. Also r = 1.
// Block 256 = 4 rows x 64 threads; thread covers cols [8tr,8tr+8) and [512+8tr,+8).
// ---------------------------------------------------------------------------
__global__ void __launch_bounds__(256, 2) exp_quant_kernel(const float* __restrict__ M) {
    int rl   = threadIdx.x >> 6;
    int tr   = threadIdx.x & 63;
    int half = tr >> 5;
    int lane = tr & 31;
    size_t r = (size_t)blockIdx.x * 4 + rl;

    const float4* __restrict__ row4 = reinterpret_cast<const float4*>(M) + r * (N / 4);

    float x[16];
    float mx = -1e30f;
#pragma unroll
    for (int k = 0; k < 4; k++) {
        int idx = (k & 1) + 2 * tr + (k >> 1) * 128;
        float4 a = row4[idx];
        float x0 = clampA(a.x), x1 = clampA(a.y), x2 = clampA(a.z), x3 = clampA(a.w);
        x[4 * k + 0] = x0; x[4 * k + 1] = x1; x[4 * k + 2] = x2; x[4 * k + 3] = x3;
        mx = fmaxf(mx, fmaxf(fmaxf(x0, x1), fmaxf(x2, x3)));
    }
#pragma unroll
    for (int o = 16; o > 0; o >>= 1)
        mx = fmaxf(mx, __shfl_xor_sync(0xFFFFFFFFu, mx, o));

    __shared__ float rm[4][2], rs[4][2];
    if (lane == 0) rm[rl][half] = mx;
    __syncthreads();
    mx = fmaxf(rm[rl][0], rm[rl][1]);

    // exp in place, partial sum
    float s = 0.0f;
#pragma unroll
    for (int k = 0; k < 16; k++) {
        x[k] = __expf(x[k] - mx);
        s += x[k];
    }
#pragma unroll
    for (int o = 16; o > 0; o >>= 1)
        s += __shfl_xor_sync(0xFFFFFFFFu, s, o);
    if (lane == 0) rs[rl][half] = s;
    __syncthreads();
    float S = rs[rl][0] + rs[rl][1];
    float inv = 1.0f / S;

    // K = exp(x - u1) = exp(x-mx)/S, bf16 packed
    uint4 w;
    uint4* __restrict__ q4 = reinterpret_cast<uint4*>(g_q) + r * 128;
    w.x = packbf(x[0] * inv, x[1] * inv);
    w.y = packbf(x[2] * inv, x[3] * inv);
    w.z = packbf(x[4] * inv, x[5] * inv);
    w.w = packbf(x[6] * inv, x[7] * inv);
    q4[tr] = w;
    w.x = packbf(x[8] * inv, x[9] * inv);
    w.y = packbf(x[10] * inv, x[11] * inv);
    w.z = packbf(x[12] * inv, x[13] * inv);
    w.w = packbf(x[14] * inv, x[15] * inv);
    q4[64 + tr] = w;

    if (tr == 0) {
        g_u[r] = mx + __logf(S);
        g_r[r] = 1.0f;
    }
}

// ---------------------------------------------------------------------------
// Exp-domain row pass: S_i = Sum_j K_ij * c_j.
//   write_u == 0:  r_i = 1/S_i            (iterations 2..9)
//   write_u == 1:  u10_i = u1_i + log S_i (iteration 10 row pass)
// Block 256 = 4 rows x 64 threads; 2 uint4 K loads + 4 float4 c loads per thread.
// ---------------------------------------------------------------------------
__global__ void __launch_bounds__(256) row_dot_kernel(int write_u) {
    int rl   = threadIdx.x >> 6;
    int tr   = threadIdx.x & 63;
    int half = tr >> 5;
    int lane = tr & 31;
    size_t r = (size_t)blockIdx.x * 4 + rl;
    int b = (int)(r >> 10);

    const uint4* __restrict__ q4 = reinterpret_cast<const uint4*>(g_q) + r * 128;
    const float4* __restrict__ c4 = reinterpret_cast<const float4*>(g_c + b * N);

    float sum = 0.0f;
    {
        uint4 q = q4[tr];
        float4 ca = c4[2 * tr];
        float4 cb = c4[2 * tr + 1];
        sum += blo(q.x) * ca.x + bhi(q.x) * ca.y;
        sum += blo(q.y) * ca.z + bhi(q.y) * ca.w;
        sum += blo(q.z) * cb.x + bhi(q.z) * cb.y;
        sum += blo(q.w) * cb.z + bhi(q.w) * cb.w;
    }
    {
        uint4 q = q4[64 + tr];
        float4 ca = c4[128 + 2 * tr];
        float4 cb = c4[129 + 2 * tr];
        sum += blo(q.x) * ca.x + bhi(q.x) * ca.y;
        sum += blo(q.y) * ca.z + bhi(q.y) * ca.w;
        sum += blo(q.z) * cb.x + bhi(q.z) * cb.y;
        sum += blo(q.w) * cb.z + bhi(q.w) * cb.w;
    }
#pragma unroll
    for (int o = 16; o > 0; o >>= 1)
        sum += __shfl_xor_sync(0xFFFFFFFFu, sum, o);

    __shared__ float rs[4][2];
    if (lane == 0) rs[rl][half] = sum;
    __syncthreads();

    if (tr == 0) {
        float S = fmaxf(rs[rl][0] + rs[rl][1], 1e-30f);
        if (write_u)
            g_u[r] = g_u[r] + __logf(S);   // u10 = u1 + log(Sum K c)
        else
            g_r[r] = 1.0f / S;
    }
}

// ---------------------------------------------------------------------------
// Exp-domain col pass partials: S_j = Sum_i K_ij * r_i over a 128-row chunk.
// Block (64,8)=512: tx = uint4 col-word (8 cols), ty = row group (rows ty+8k, k<16).
// Grid (2, NCHUNK, NB).
// ---------------------------------------------------------------------------
__global__ void __launch_bounds__(512, 2) col_sum_kernel() {
    int b  = blockIdx.z;
    int tx = threadIdx.x;           // 0..63
    int ty = threadIdx.y;           // 0..7
    int i0 = blockIdx.y * 128;
    int c  = blockIdx.x * 64 + tx;  // uint4 index within row [0,128)

    __shared__ float sr[128];
    __shared__ float red[8][512];

    int t = ty * 64 + tx;
    if (t < 128)
        sr[t] = g_r[b * N + i0 + t];
    __syncthreads();

    const uint4* __restrict__ q4 = reinterpret_cast<const uint4*>(g_q);

    float acc[8] = {0.f, 0.f, 0.f, 0.f, 0.f, 0.f, 0.f, 0.f};
#pragma unroll
    for (int k = 0; k < 16; k++) {
        int i = ty + 8 * k;
        uint4 q = q4[((size_t)b * N + i0 + i) * 128 + c];
        float rr = sr[i];
        acc[0] += blo(q.x) * rr; acc[1] += bhi(q.x) * rr;
        acc[2] += blo(q.y) * rr; acc[3] += bhi(q.y) * rr;
        acc[4] += blo(q.z) * rr; acc[5] += bhi(q.z) * rr;
        acc[6] += blo(q.w) * rr; acc[7] += bhi(q.w) * rr;
    }

#pragma unroll
    for (int q = 0; q < 8; q++)
        red[ty][q * 64 + tx] = acc[q];
    __syncthreads();

    float S = red[0][t];
#pragma unroll
    for (int k = 1; k < 8; k++)
        S += red[k][t];
    int j = blockIdx.x * 512 + tx * 8 + ty;
    g_ps[((size_t)b * NCHUNK + blockIdx.y) * N + j] = S;
}

// Merge NCHUNK partials: c_j = 1/S_j, v_j = log S_j.
__global__ void __launch_bounds__(256) combine_kernel() {
    int t = blockIdx.x * 256 + threadIdx.x;   // 0..NB*N-1
    int b = t >> 10;
    int j = t & (N - 1);

    size_t pb = (size_t)b * NCHUNK * N + j;
    float S = g_ps[pb];
#pragma unroll
    for (int cc = 1; cc < NCHUNK; cc++)
        S += g_ps[pb + (size_t)cc * N];
    S = fmaxf(S, 1e-30f);
    g_c[t] = 1.0f / S;
    g_v[t] = __logf(S);
}

// ---------------------------------------------------------------------------
// EXACT last col pass fused with output write (iteration 10 col + exp).
// Uses exact A elementwise; only u10 carries (smooth) quantization error.
// ---------------------------------------------------------------------------
__global__ void __launch_bounds__(1024) col_lse_finalize_kernel(const float* __restrict__ M,
                                                                float* __restrict__ out) {
    int b = blockIdx.y;
    int cx = threadIdx.x;
    int y  = threadIdx.y;
    int j = blockIdx.x * 32 + cx;

    __shared__ float us[N];
    __shared__ float sm_m[32][33];
    __shared__ float sm_s[32][33];

    us[y * 32 + cx] = g_u[b * N + y * 32 + cx];
    __syncthreads();

    const float* __restrict__ base = M + (size_t)b * N * N + j;

    float xv[32];
    float mx = -1e30f;
#pragma unroll
    for (int k = 0; k < 32; k++) {
        int i = y + 32 * k;
        float a = base[(size_t)i * N];
        float t = clampA(a) - us[i];
        xv[k] = t;
        mx = fmaxf(mx, t);
    }

    sm_m[y][cx] = mx;
    __syncthreads();

    float MX = sm_m[0][cx];
#pragma unroll
    for (int k = 1; k < 32; k++)
        MX = fmaxf(MX, sm_m[k][cx]);

    float s = 0.0f;
#pragma unroll
    for (int k = 0; k < 32; k++)
        s += __expf(xv[k] - MX);

    sm_s[y][cx] = s;
    __syncthreads();

    float SS = sm_s[0][cx];
#pragma unroll
    for (int k = 1; k < 32; k++)
        SS += sm_s[k][cx];
    float V = MX + __logf(SS);

    float* __restrict__ obase = out + (size_t)b * N * N + j;
#pragma unroll
    for (int k = 0; k < 32; k++) {
        int i = y + 32 * k;
        obase[(size_t)i * N] = __expf(xv[k] - V);
    }
}

extern "C" void kernel_launch(void* const* d_in, const int* in_sizes, int n_in,
                              void* d_out, int out_size) {
    const float* M = (const float*)d_in[0];
    float* out = (float*)d_out;

    // Iteration 1 row pass (exact) + K = exp(A - u1) in bf16 + r = 1
    exp_quant_kernel<<<(NB * N) / 4, 256>>>(M);

    // Col passes 1..9 (exp domain); row passes 2..9 update r, row pass 10 writes u10
    for (int it = 0; it < ITERS - 1; it++) {
        col_sum_kernel<<<dim3(2, NCHUNK, NB), dim3(64, 8)>>>();
        combine_kernel<<<(NB * N) / 256, 256>>>();
        row_dot_kernel<<<(NB * N) / 4, 256>>>(it == ITERS - 2 ? 1 : 0);
    }

    // Iteration 10 col pass + output (exact A elementwise)
    col_lse_finalize_kernel<<<dim3(N / 32, NB), dim3(32, 32)>>>(M, out);
}

// round 10
// speedup vs baseline: 2.1810x; 1.1347x over previous
#include <cuda_runtime.h>
#include <cuda_bf16.h>
#include <math.h>

#define NB 64
#define N 1024
#define ITERS 10
#define NCHUNK 8

// Scratch (allocation-free, static device memory)
__device__ __align__(16) float g_u[NB * N];     // u1, later u10
__device__ __align__(16) float g_v[NB * N];     // log-domain col potential
__device__ __align__(16) float g_r[NB * N];     // exp-domain row scaling
__device__ __align__(16) float g_c[NB * N];     // exp-domain col scaling
__device__ __align__(16) float g_ps[NB * NCHUNK * N];
// K = exp(A - u1) stored as bf16
__device__ __align__(16) unsigned short g_q[(size_t)NB * N * N];

__device__ __forceinline__ float clampA(float m) {
    return fminf(fmaxf(m, -25.0f), 25.0f) * 10.0f;
}
__device__ __forceinline__ float blo(unsigned int w) { return __uint_as_float(w << 16); }
__device__ __forceinline__ float bhi(unsigned int w) { return __uint_as_float(w & 0xFFFF0000u); }
__device__ __forceinline__ unsigned int packbf(float lo, float hi) {
    __nv_bfloat162 h = __floats2bfloat162_rn(lo, hi);
    return *reinterpret_cast<unsigned int*>(&h);
}

// ---------------------------------------------------------------------------
// Pass 0: exact row-LSE (u1) + K = exp(A - u1) in bf16. Also r = 1.
// ---------------------------------------------------------------------------
__global__ void __launch_bounds__(256, 2) exp_quant_kernel(const float* __restrict__ M) {
    int rl   = threadIdx.x >> 6;
    int tr   = threadIdx.x & 63;
    int half = tr >> 5;
    int lane = tr & 31;
    size_t r = (size_t)blockIdx.x * 4 + rl;

    const float4* __restrict__ row4 = reinterpret_cast<const float4*>(M) + r * (N / 4);

    float x[16];
    float mx = -1e30f;
#pragma unroll
    for (int k = 0; k < 4; k++) {
        int idx = (k & 1) + 2 * tr + (k >> 1) * 128;
        float4 a = row4[idx];
        float x0 = clampA(a.x), x1 = clampA(a.y), x2 = clampA(a.z), x3 = clampA(a.w);
        x[4 * k + 0] = x0; x[4 * k + 1] = x1; x[4 * k + 2] = x2; x[4 * k + 3] = x3;
        mx = fmaxf(mx, fmaxf(fmaxf(x0, x1), fmaxf(x2, x3)));
    }
#pragma unroll
    for (int o = 16; o > 0; o >>= 1)
        mx = fmaxf(mx, __shfl_xor_sync(0xFFFFFFFFu, mx, o));

    __shared__ float rm[4][2], rs[4][2];
    if (lane == 0) rm[rl][half] = mx;
    __syncthreads();
    mx = fmaxf(rm[rl][0], rm[rl][1]);

    float s = 0.0f;
#pragma unroll
    for (int k = 0; k < 16; k++) {
        x[k] = __expf(x[k] - mx);
        s += x[k];
    }
#pragma unroll
    for (int o = 16; o > 0; o >>= 1)
        s += __shfl_xor_sync(0xFFFFFFFFu, s, o);
    if (lane == 0) rs[rl][half] = s;
    __syncthreads();
    float S = rs[rl][0] + rs[rl][1];
    float inv = 1.0f / S;

    uint4 w;
    uint4* __restrict__ q4 = reinterpret_cast<uint4*>(g_q) + r * 128;
    w.x = packbf(x[0] * inv, x[1] * inv);
    w.y = packbf(x[2] * inv, x[3] * inv);
    w.z = packbf(x[4] * inv, x[5] * inv);
    w.w = packbf(x[6] * inv, x[7] * inv);
    q4[tr] = w;
    w.x = packbf(x[8] * inv, x[9] * inv);
    w.y = packbf(x[10] * inv, x[11] * inv);
    w.z = packbf(x[12] * inv, x[13] * inv);
    w.w = packbf(x[14] * inv, x[15] * inv);
    q4[64 + tr] = w;

    if (tr == 0) {
        g_u[r] = mx + __logf(S);
        g_r[r] = 1.0f;
    }
}

// ---------------------------------------------------------------------------
// Exp-domain row pass: S_i = Sum_j K_ij * c_j. c amortized over 4 rows/thread.
// Block 256 = 4 row-groups x 64 threads; block covers 16 rows (one batch).
//   write_u == 0:  r_i = 1/S_i            (iterations 2..9)
//   write_u == 1:  u10_i = u1_i + log S_i (iteration 10 row pass)
// ---------------------------------------------------------------------------
__global__ void __launch_bounds__(256) row_dot_kernel(int write_u) {
    int rg   = threadIdx.x >> 6;        // 0..3 row-group of 4 rows
    int tr   = threadIdx.x & 63;
    int half = tr >> 5;
    int lane = tr & 31;
    size_t rbase = (size_t)blockIdx.x * 16 + rg * 4;
    int b = (int)(rbase >> 10);

    const float4* __restrict__ c4 = reinterpret_cast<const float4*>(g_c + b * N);
    float4 ca0 = c4[2 * tr];
    float4 cb0 = c4[2 * tr + 1];
    float4 ca1 = c4[128 + 2 * tr];
    float4 cb1 = c4[129 + 2 * tr];

    float sum[4];
#pragma unroll
    for (int rr = 0; rr < 4; rr++) {
        const uint4* __restrict__ q4 = reinterpret_cast<const uint4*>(g_q) + (rbase + rr) * 128;
        uint4 qa = q4[tr];
        uint4 qb = q4[64 + tr];
        float s = 0.0f;
        s += blo(qa.x) * ca0.x + bhi(qa.x) * ca0.y;
        s += blo(qa.y) * ca0.z + bhi(qa.y) * ca0.w;
        s += blo(qa.z) * cb0.x + bhi(qa.z) * cb0.y;
        s += blo(qa.w) * cb0.z + bhi(qa.w) * cb0.w;
        s += blo(qb.x) * ca1.x + bhi(qb.x) * ca1.y;
        s += blo(qb.y) * ca1.z + bhi(qb.y) * ca1.w;
        s += blo(qb.z) * cb1.x + bhi(qb.z) * cb1.y;
        s += blo(qb.w) * cb1.z + bhi(qb.w) * cb1.w;
        sum[rr] = s;
    }
#pragma unroll
    for (int rr = 0; rr < 4; rr++) {
#pragma unroll
        for (int o = 16; o > 0; o >>= 1)
            sum[rr] += __shfl_xor_sync(0xFFFFFFFFu, sum[rr], o);
    }

    __shared__ float rs[4][4][2];
    if (lane == 0) {
#pragma unroll
        for (int rr = 0; rr < 4; rr++)
            rs[rg][rr][half] = sum[rr];
    }
    __syncthreads();

    if (threadIdx.x < 16) {
        int g = threadIdx.x >> 2, rr = threadIdx.x & 3;
        size_t r = (size_t)blockIdx.x * 16 + g * 4 + rr;
        float S = fmaxf(rs[g][rr][0] + rs[g][rr][1], 1e-30f);
        if (write_u)
            g_u[r] = g_u[r] + __logf(S);
        else
            g_r[r] = 1.0f / S;
    }
}

// ---------------------------------------------------------------------------
// Exp-domain col pass partials: S_j = Sum_i K_ij * r_i over a 128-row chunk.
// Block (64,8)=512. Grid (2, NCHUNK, NB).
// ---------------------------------------------------------------------------
__global__ void __launch_bounds__(512, 2) col_sum_kernel() {
    int b  = blockIdx.z;
    int tx = threadIdx.x;
    int ty = threadIdx.y;
    int i0 = blockIdx.y * 128;
    int c  = blockIdx.x * 64 + tx;

    __shared__ float sr[128];
    __shared__ float red[8][512];

    int t = ty * 64 + tx;
    if (t < 128)
        sr[t] = g_r[b * N + i0 + t];
    __syncthreads();

    const uint4* __restrict__ q4 = reinterpret_cast<const uint4*>(g_q);

    float acc[8] = {0.f, 0.f, 0.f, 0.f, 0.f, 0.f, 0.f, 0.f};
#pragma unroll
    for (int k = 0; k < 16; k++) {
        int i = ty + 8 * k;
        uint4 q = q4[((size_t)b * N + i0 + i) * 128 + c];
        float rr = sr[i];
        acc[0] += blo(q.x) * rr; acc[1] += bhi(q.x) * rr;
        acc[2] += blo(q.y) * rr; acc[3] += bhi(q.y) * rr;
        acc[4] += blo(q.z) * rr; acc[5] += bhi(q.z) * rr;
        acc[6] += blo(q.w) * rr; acc[7] += bhi(q.w) * rr;
    }

#pragma unroll
    for (int q = 0; q < 8; q++)
        red[ty][q * 64 + tx] = acc[q];
    __syncthreads();

    float S = red[0][t];
#pragma unroll
    for (int k = 1; k < 8; k++)
        S += red[k][t];
    int j = blockIdx.x * 512 + tx * 8 + ty;
    g_ps[((size_t)b * NCHUNK + blockIdx.y) * N + j] = S;
}

// Merge NCHUNK partials: c_j = 1/S_j, v_j = log S_j.
__global__ void __launch_bounds__(256) combine_kernel() {
    int t = blockIdx.x * 256 + threadIdx.x;
    size_t pb = (size_t)(t >> 10) * NCHUNK * N + (t & (N - 1));
    float S = g_ps[pb];
#pragma unroll
    for (int cc = 1; cc < NCHUNK; cc++)
        S += g_ps[pb + (size_t)cc * N];
    S = fmaxf(S, 1e-30f);
    g_c[t] = 1.0f / S;
    g_v[t] = __logf(S);
}

// ---------------------------------------------------------------------------
// EXACT last col pass fused with output write (iteration 10 col + exp).
// float4 layout: thread (tx,ty) = float4-col tx (of 8), rows ty+128k (k<8).
// Block 1024 = tile 32 cols x 1024 rows. Grid (32, NB).
// ---------------------------------------------------------------------------
__global__ void __launch_bounds__(1024) col_lse_finalize_kernel(const float* __restrict__ M,
                                                                float* __restrict__ out) {
    int b  = blockIdx.y;
    int tx = threadIdx.x & 7;       // float4-col within tile
    int ty = threadIdx.x >> 3;      // 0..127 row group
    int lane = threadIdx.x & 31;
    int wid  = threadIdx.x >> 5;    // 0..31
    int j4 = blockIdx.x * 8 + tx;   // global float4-col

    __shared__ float us[N];
    __shared__ float4 redm[32][8];
    __shared__ float4 reds[32][8];

    us[threadIdx.x] = g_u[b * N + threadIdx.x];
    __syncthreads();

    const float4* __restrict__ base = reinterpret_cast<const float4*>(M)
                                      + (size_t)b * N * (N / 4) + j4;

    float4 xv[8];
    float4 mx = make_float4(-1e30f, -1e30f, -1e30f, -1e30f);
#pragma unroll
    for (int k = 0; k < 8; k++) {
        int i = ty + 128 * k;
        float4 a = base[(size_t)i * (N / 4)];
        float u = us[i];
        float4 t;
        t.x = clampA(a.x) - u; t.y = clampA(a.y) - u;
        t.z = clampA(a.z) - u; t.w = clampA(a.w) - u;
        xv[k] = t;
        mx.x = fmaxf(mx.x, t.x); mx.y = fmaxf(mx.y, t.y);
        mx.z = fmaxf(mx.z, t.z); mx.w = fmaxf(mx.w, t.w);
    }

    // warp pre-reduce over the 4 row-lanes (offsets 8, 16 preserve tx = lane&7)
#pragma unroll
    for (int o = 8; o <= 16; o <<= 1) {
        mx.x = fmaxf(mx.x, __shfl_xor_sync(0xFFFFFFFFu, mx.x, o));
        mx.y = fmaxf(mx.y, __shfl_xor_sync(0xFFFFFFFFu, mx.y, o));
        mx.z = fmaxf(mx.z, __shfl_xor_sync(0xFFFFFFFFu, mx.z, o));
        mx.w = fmaxf(mx.w, __shfl_xor_sync(0xFFFFFFFFu, mx.w, o));
    }
    if (lane < 8) redm[wid][lane] = mx;
    __syncthreads();
    // tree over 32 warps
#pragma unroll
    for (int h = 16; h > 0; h >>= 1) {
        if (threadIdx.x < (unsigned)(h * 8)) {
            int w = threadIdx.x >> 3, x = threadIdx.x & 7;
            float4 a = redm[w][x], c = redm[w + h][x];
            a.x = fmaxf(a.x, c.x); a.y = fmaxf(a.y, c.y);
            a.z = fmaxf(a.z, c.z); a.w = fmaxf(a.w, c.w);
            redm[w][x] = a;
        }
        __syncthreads();
    }
    float4 MX = redm[0][tx];

    float4 s = make_float4(0.f, 0.f, 0.f, 0.f);
#pragma unroll
    for (int k = 0; k < 8; k++) {
        s.x += __expf(xv[k].x - MX.x);
        s.y += __expf(xv[k].y - MX.y);
        s.z += __expf(xv[k].z - MX.z);
        s.w += __expf(xv[k].w - MX.w);
    }
#pragma unroll
    for (int o = 8; o <= 16; o <<= 1) {
        s.x += __shfl_xor_sync(0xFFFFFFFFu, s.x, o);
        s.y += __shfl_xor_sync(0xFFFFFFFFu, s.y, o);
        s.z += __shfl_xor_sync(0xFFFFFFFFu, s.z, o);
        s.w += __shfl_xor_sync(0xFFFFFFFFu, s.w, o);
    }
    if (lane < 8) reds[wid][lane] = s;
    __syncthreads();
#pragma unroll
    for (int h = 16; h > 0; h >>= 1) {
        if (threadIdx.x < (unsigned)(h * 8)) {
            int w = threadIdx.x >> 3, x = threadIdx.x & 7;
            float4 a = reds[w][x], c = reds[w + h][x];
            a.x += c.x; a.y += c.y; a.z += c.z; a.w += c.w;
            reds[w][x] = a;
        }
        __syncthreads();
    }
    float4 SS = reds[0][tx];

    float4 V;
    V.x = MX.x + __logf(SS.x);
    V.y = MX.y + __logf(SS.y);
    V.z = MX.z + __logf(SS.z);
    V.w = MX.w + __logf(SS.w);

    float4* __restrict__ obase = reinterpret_cast<float4*>(out)
                                 + (size_t)b * N * (N / 4) + j4;
#pragma unroll
    for (int k = 0; k < 8; k++) {
        int i = ty + 128 * k;
        float4 o;
        o.x = __expf(xv[k].x - V.x);
        o.y = __expf(xv[k].y - V.y);
        o.z = __expf(xv[k].z - V.z);
        o.w = __expf(xv[k].w - V.w);
        obase[(size_t)i * (N / 4)] = o;
    }
}

extern "C" void kernel_launch(void* const* d_in, const int* in_sizes, int n_in,
                              void* d_out, int out_size) {
    const float* M = (const float*)d_in[0];
    float* out = (float*)d_out;

    exp_quant_kernel<<<(NB * N) / 4, 256>>>(M);

    for (int it = 0; it < ITERS - 1; it++) {
        col_sum_kernel<<<dim3(2, NCHUNK, NB), dim3(64, 8)>>>();
        combine_kernel<<<(NB * N) / 256, 256>>>();
        row_dot_kernel<<<(NB * N) / 16, 256>>>(it == ITERS - 2 ? 1 : 0);
    }

    col_lse_finalize_kernel<<<dim3(N / 32, NB), 1024>>>(M, out);
}